// round 13
// baseline (speedup 1.0000x reference)
#include <cuda_runtime.h>
#include <cuda_fp16.h>
#include <math.h>
#include <stdint.h>

// Problem constants
#define BB 256
#define LL 256
#define DD 512
#define HH 8
#define DHH 64
#define NLAYER 6
#define FFD 2048
#define TT (BB*LL)          // 65536 tokens
#define NATOM 32768
#define QKVD 1536

// ---------------- scratch (device globals; no allocation allowed) -----------
__device__ float  g_h  [(size_t)TT*DD];
__device__ __half g_hn [(size_t)TT*DD];
__device__ __half g_qkv[(size_t)TT*QKVD];      // 201 MB
__device__ __half g_ctx[(size_t)TT*DD];
__device__ __half g_ff [(size_t)TT*FFD];       // 268 MB
#define WT_LSTRIDE 3145728
__device__ __half g_wt [(size_t)NLAYER*WT_LSTRIDE];  // 37.7 MB
__device__ float  g_bqkv[(size_t)NLAYER*QKVD];

// ---------------- small helpers ----------------------------------------------
__device__ __forceinline__ uint32_t smem_u32(const void* p) {
    uint32_t a;
    asm("{ .reg .u64 t; cvta.to.shared.u64 t, %1; cvt.u32.u64 %0, t; }" : "=r"(a) : "l"(p));
    return a;
}
__device__ __forceinline__ void cp_async16(uint32_t dst, const void* src) {
    asm volatile("cp.async.cg.shared.global [%0], [%1], 16;" :: "r"(dst), "l"(src) : "memory");
}
__device__ __forceinline__ void cp_commit() {
    asm volatile("cp.async.commit_group;" ::: "memory");
}
template<int N>
__device__ __forceinline__ void cp_wait() {
    asm volatile("cp.async.wait_group %0;" :: "n"(N) : "memory");
}
__device__ __forceinline__ void mma_f16(float& d0, float& d1, float& d2, float& d3,
                                        uint32_t a0, uint32_t a1, uint32_t a2, uint32_t a3,
                                        uint32_t b0, uint32_t b1) {
    asm volatile(
        "mma.sync.aligned.m16n8k16.row.col.f32.f16.f16.f32 "
        "{%0,%1,%2,%3}, {%4,%5,%6,%7}, {%8,%9}, {%0,%1,%2,%3};"
        : "+f"(d0), "+f"(d1), "+f"(d2), "+f"(d3)
        : "r"(a0), "r"(a1), "r"(a2), "r"(a3), "r"(b0), "r"(b1));
}
__device__ __forceinline__ void ldmatrix_x4(uint32_t& r0, uint32_t& r1, uint32_t& r2, uint32_t& r3,
                                            uint32_t addr) {
    asm volatile("ldmatrix.sync.aligned.m8n8.x4.shared.b16 {%0,%1,%2,%3}, [%4];"
                 : "=r"(r0), "=r"(r1), "=r"(r2), "=r"(r3) : "r"(addr));
}
__device__ __forceinline__ void ldmatrix_x4_trans(uint32_t& r0, uint32_t& r1, uint32_t& r2, uint32_t& r3,
                                                  uint32_t addr) {
    asm volatile("ldmatrix.sync.aligned.m8n8.x4.trans.shared.b16 {%0,%1,%2,%3}, [%4];"
                 : "=r"(r0), "=r"(r1), "=r"(r2), "=r"(r3) : "r"(addr));
}
__device__ __forceinline__ uint32_t pack_h2(float a, float b) {
    __half2 h = __floats2half2_rn(a, b);
    return *(uint32_t*)&h;
}
// output store helpers
__device__ __forceinline__ void store_pair(float* p, float vx, float vy) {
    *(float2*)p = make_float2(vx, vy);
}
__device__ __forceinline__ void store_pair(__half* p, float vx, float vy) {
    *(__half2*)p = __floats2half2_rn(vx, vy);
}
__device__ __forceinline__ float warp_sum(float v) {
    #pragma unroll
    for (int o = 16; o; o >>= 1) v += __shfl_xor_sync(0xffffffffu, v, o);
    return v;
}

// ---------------- embedding -------------------------------------------------
__global__ void embed_kernel(const int* __restrict__ x, const float* __restrict__ emb,
                             const float* __restrict__ rate1, float* __restrict__ h) {
    int idx = blockIdx.x * blockDim.x + threadIdx.x;
    int t = idx / (DD/4);
    int c = idx % (DD/4);
    int b = t / LL, l = t % LL;
    int tok = x[l*BB + b];
    float4 e = ((const float4*)(emb + (size_t)tok*DD))[c];
    float r = rate1[0];
    ((float4*)(h + (size_t)t*DD))[c] = make_float4(r*e.x, r*e.y, r*e.z, r*e.w);
}

__global__ void atom_kernel(const float* __restrict__ coord, const int* __restrict__ atok,
                            const int* __restrict__ aidx, const int* __restrict__ bidx,
                            const float* __restrict__ emb, const float* __restrict__ cw,
                            const float* __restrict__ cb, const float* __restrict__ rate2,
                            float* __restrict__ h) {
    int a = blockIdx.x;
    int tok = atok[a];
    float c0 = coord[a*3+0], c1 = coord[a*3+1], c2 = coord[a*3+2];
    size_t row = (size_t)(bidx[a]*LL + aidx[a] + 1) * DD;
    float r = rate2[0];
    for (int i = threadIdx.x; i < DD; i += blockDim.x) {
        float val = emb[(size_t)tok*DD + i] + c0*cw[i] + c1*cw[DD+i] + c2*cw[2*DD+i] + cb[i];
        h[row + i] += r * val;
    }
}

// ---------------- warp-per-row layernorm (half out; no barriers) -------------
__global__ void __launch_bounds__(256)
ln_kernel(const float* __restrict__ in, __half* __restrict__ out,
          const float* __restrict__ g, const float* __restrict__ bt) {
    int wid = threadIdx.x >> 5, lane = threadIdx.x & 31;
    size_t row = (size_t)blockIdx.x*8 + wid;
    const float4* p = (const float4*)(in + row*DD);
    float4 v[4];
    float s = 0.f;
    #pragma unroll
    for (int k = 0; k < 4; k++) {
        v[k] = p[lane + k*32];
        s += (v[k].x + v[k].y) + (v[k].z + v[k].w);
    }
    float mean = warp_sum(s) * (1.0f/DD);
    float s2 = 0.f;
    #pragma unroll
    for (int k = 0; k < 4; k++) {
        v[k].x -= mean; v[k].y -= mean; v[k].z -= mean; v[k].w -= mean;
        s2 += (v[k].x*v[k].x + v[k].y*v[k].y) + (v[k].z*v[k].z + v[k].w*v[k].w);
    }
    float rs = rsqrtf(warp_sum(s2) * (1.0f/DD) + 1e-6f);
    const float4* gp = (const float4*)g;
    const float4* bp = (const float4*)bt;
    #pragma unroll
    for (int k = 0; k < 4; k++) {
        int idx = lane + k*32;
        float4 gv = gp[idx], bv = bp[idx];
        uint2 o2;
        o2.x = pack_h2(v[k].x*rs*gv.x + bv.x, v[k].y*rs*gv.y + bv.y);
        o2.y = pack_h2(v[k].z*rs*gv.z + bv.z, v[k].w*rs*gv.w + bv.w);
        *(uint2*)(out + row*DD + (size_t)idx*4) = o2;
    }
}

// final LN + transpose [B,L,D] -> [L,B,D], warp-per-row
__global__ void __launch_bounds__(256)
lnf_kernel(const float* __restrict__ in, float* __restrict__ out,
           const float* __restrict__ g, const float* __restrict__ bt) {
    int wid = threadIdx.x >> 5, lane = threadIdx.x & 31;
    size_t t = (size_t)blockIdx.x*8 + wid;
    int b = (int)(t / LL), l = (int)(t % LL);
    const float4* p = (const float4*)(in + t*DD);
    float4 v[4];
    float s = 0.f;
    #pragma unroll
    for (int k = 0; k < 4; k++) {
        v[k] = p[lane + k*32];
        s += (v[k].x + v[k].y) + (v[k].z + v[k].w);
    }
    float mean = warp_sum(s) * (1.0f/DD);
    float s2 = 0.f;
    #pragma unroll
    for (int k = 0; k < 4; k++) {
        v[k].x -= mean; v[k].y -= mean; v[k].z -= mean; v[k].w -= mean;
        s2 += (v[k].x*v[k].x + v[k].y*v[k].y) + (v[k].z*v[k].z + v[k].w*v[k].w);
    }
    float rs = rsqrtf(warp_sum(s2) * (1.0f/DD) + 1e-6f);
    const float4* gp = (const float4*)g;
    const float4* bp = (const float4*)bt;
    float4* op = (float4*)(out + (size_t)(l*BB + b)*DD);
    #pragma unroll
    for (int k = 0; k < 4; k++) {
        int idx = lane + k*32;
        float4 gv = gp[idx], bv = bp[idx];
        op[idx] = make_float4(v[k].x*rs*gv.x + bv.x, v[k].y*rs*gv.y + bv.y,
                              v[k].z*rs*gv.z + bv.z, v[k].w*rs*gv.w + bv.w);
    }
}

// ---------------- weight transpose + fp16 convert, batched over layers ------
__global__ void transpose_f16_b(const float* __restrict__ W, __half* __restrict__ Wt,
                                int K, int N, size_t w_stride, size_t wt_stride) {
    __shared__ float t[32][33];
    const float* Wl = W + (size_t)blockIdx.z * w_stride;
    __half* Wtl = Wt + (size_t)blockIdx.z * wt_stride;
    int k0 = blockIdx.x*32, n0 = blockIdx.y*32;
    int tx = threadIdx.x, ty = threadIdx.y;
    for (int i = ty; i < 32; i += 8)
        t[i][tx] = Wl[(size_t)(k0+i)*N + n0 + tx];
    __syncthreads();
    for (int i = ty; i < 32; i += 8)
        Wtl[(size_t)(n0+i)*K + k0 + tx] = __float2half(t[tx][i]);
}

// ---------------- concat QKV bias --------------------------------------------
__global__ void concat_bias(const float* __restrict__ bq, const float* __restrict__ bk,
                            const float* __restrict__ bv, float* __restrict__ bqkv) {
    int l = blockIdx.y;
    int i = blockIdx.x*256 + threadIdx.x;
    float v;
    if (i < 512)       v = bq[l*DD + i];
    else if (i < 1024) v = bk[l*DD + i - 512];
    else               v = bv[l*DD + i - 1024];
    bqkv[(size_t)l*QKVD + i] = v;
}

// ---------------- fp16 mma GEMM: C[M,N] = A[M,K] @ Wt[N,K]^T + bias ----------
// BM=BN=128, BK=64 halves, 256 threads = 8 warps (4 M x 2 N), warp tile 32x64.
// __launch_bounds__(256,2): 2 CTAs/SM to overlap sync/load phases.
#define SROWH 72
#define TILEH (128*SROWH)
#define SMEM_GEMM (4*TILEH*2)          // 73728 bytes

template<int RELU, int RESID, typename OutT>
__global__ void __launch_bounds__(256, 2)
mma_gemm(int K, const __half* __restrict__ A, const __half* __restrict__ Bt,
         const float* __restrict__ bias, const float* __restrict__ Res,
         OutT* __restrict__ C, int N) {
    extern __shared__ __align__(16) __half hdyn[];
    __half* sA = hdyn;
    __half* sB = hdyn + 2*TILEH;
    uint32_t sA_u = smem_u32(sA);
    uint32_t sB_u = smem_u32(sB);

    int tid = threadIdx.x;
    int wid = tid >> 5, lane = tid & 31;
    int warp_m = wid >> 1;
    int warp_n = wid & 1;
    int bm = blockIdx.y, bn = blockIdx.x;

    const __half* Abase = A  + (size_t)bm*128*K;
    const __half* Bbase = Bt + (size_t)bn*128*K;

    auto load_tile = [&](int buf, int c) {
        const __half* Ap = Abase + c*64;
        const __half* Bp = Bbase + c*64;
        uint32_t sa = sA_u + (uint32_t)buf*TILEH*2;
        uint32_t sb = sB_u + (uint32_t)buf*TILEH*2;
        #pragma unroll
        for (int i = 0; i < 4; i++) {
            int cid = tid + i*256;
            int row = cid >> 3;
            int kc  = cid & 7;
            uint32_t soff = (uint32_t)(row*144 + kc*16);
            cp_async16(sa + soff, Ap + (size_t)row*K + kc*8);
            cp_async16(sb + soff, Bp + (size_t)row*K + kc*8);
        }
    };

    float acc[2][8][4];
    #pragma unroll
    for (int mt = 0; mt < 2; mt++)
        #pragma unroll
        for (int nt = 0; nt < 8; nt++)
            #pragma unroll
            for (int j = 0; j < 4; j++) acc[mt][nt][j] = 0.f;

    int NC = K >> 6;
    load_tile(0, 0);
    cp_commit();

    int r = lane >> 2;      // 0..7
    int cq = lane & 3;      // 0..3
    int mi = lane >> 3, lr = lane & 7;
    uint32_t aoff[2], boff[4];
    #pragma unroll
    for (int mt = 0; mt < 2; mt++)
        aoff[mt] = (uint32_t)(((warp_m*32 + mt*16 + (mi & 1)*8 + lr)*SROWH + (mi >> 1)*8) * 2);
    #pragma unroll
    for (int ntp = 0; ntp < 4; ntp++)
        boff[ntp] = (uint32_t)(((warp_n*64 + ntp*16 + (mi >> 1)*8 + lr)*SROWH + (mi & 1)*8) * 2);

    for (int c = 0; c < NC; c++) {
        int buf = c & 1;
        if (c + 1 < NC) {
            load_tile(buf ^ 1, c + 1);
            cp_commit();
            cp_wait<1>();
        } else {
            cp_wait<0>();
        }
        __syncthreads();

        uint32_t tA_u = sA_u + (uint32_t)buf*TILEH*2;
        uint32_t tB_u = sB_u + (uint32_t)buf*TILEH*2;
        #pragma unroll
        for (int kk = 0; kk < 4; kk++) {
            uint32_t kof = (uint32_t)(kk*16*2);
            uint32_t af[2][4];
            ldmatrix_x4(af[0][0], af[0][1], af[0][2], af[0][3], tA_u + aoff[0] + kof);
            ldmatrix_x4(af[1][0], af[1][1], af[1][2], af[1][3], tA_u + aoff[1] + kof);
            #pragma unroll
            for (int ntp = 0; ntp < 4; ntp++) {
                uint32_t b0, b1, b2, b3;
                ldmatrix_x4(b0, b1, b2, b3, tB_u + boff[ntp] + kof);
                #pragma unroll
                for (int mt = 0; mt < 2; mt++) {
                    mma_f16(acc[mt][2*ntp][0],   acc[mt][2*ntp][1],   acc[mt][2*ntp][2],   acc[mt][2*ntp][3],
                            af[mt][0], af[mt][1], af[mt][2], af[mt][3], b0, b1);
                    mma_f16(acc[mt][2*ntp+1][0], acc[mt][2*ntp+1][1], acc[mt][2*ntp+1][2], acc[mt][2*ntp+1][3],
                            af[mt][0], af[mt][1], af[mt][2], af[mt][3], b2, b3);
                }
            }
        }
        __syncthreads();
    }

    #pragma unroll
    for (int mt = 0; mt < 2; mt++) {
        size_t m0 = (size_t)bm*128 + warp_m*32 + mt*16 + r;
        #pragma unroll
        for (int nt = 0; nt < 8; nt++) {
            int n = bn*128 + warp_n*64 + nt*8 + 2*cq;
            float2 bs = *(const float2*)(bias + n);
            #pragma unroll
            for (int half_i = 0; half_i < 2; half_i++) {
                size_t m = m0 + half_i*8;
                float vx = acc[mt][nt][half_i*2 + 0] + bs.x;
                float vy = acc[mt][nt][half_i*2 + 1] + bs.y;
                if (RESID) {
                    float2 rr = *(const float2*)(Res + m*N + n);
                    vx += rr.x; vy += rr.y;
                }
                if (RELU) {
                    vx = fmaxf(vx, 0.f);
                    vy = fmaxf(vy, 0.f);
                }
                store_pair(C + m*N + n, vx, vy);
            }
        }
    }
}

// ---------------- fp16 mma flash attention -----------------------------------
// One CTA per (b,h): 8 warps x 32 Q rows = all 256 Q rows. K/V tiles loaded
// once per head (was twice). Two online-softmax states per warp (Q halves).
#define FVS 72

__global__ void __launch_bounds__(256)
flash_kernel(const __half* __restrict__ qkv, const int* __restrict__ x,
             __half* __restrict__ ctx) {
    __shared__ __align__(16) __half Ks[64*FVS];
    __shared__ __align__(16) __half Vs[64*FVS];
    __shared__ int padf[256];

    int bh = blockIdx.x, b = bh >> 3, h = bh & 7;
    int tid = threadIdx.x;
    int wid = tid >> 5, lane = tid & 31;
    int r = lane >> 2, c2 = (lane & 3) * 2;
    int mi2 = lane >> 3, lr2 = lane & 7;

    // pad flags for all 256 keys, once
    padf[tid] = (x[tid*BB + b] == 0);

    // Q fragments for both 128-row halves (pre-scaled by 1/8 exactly)
    uint32_t qf[2][4][4];
    {
        const __half2 sc = __float2half2_rn(0.125f);
        #pragma unroll
        for (int qh = 0; qh < 2; qh++) {
            size_t row0 = (size_t)(b*LL + qh*128 + wid*16 + r) * QKVD + h*DHH;
            #pragma unroll
            for (int k = 0; k < 4; k++) {
                __half2 v0 = *(const __half2*)(qkv + row0 + k*16 + c2);
                __half2 v1 = *(const __half2*)(qkv + row0 + 8*QKVD + k*16 + c2);
                __half2 v2 = *(const __half2*)(qkv + row0 + k*16 + 8 + c2);
                __half2 v3 = *(const __half2*)(qkv + row0 + 8*QKVD + k*16 + 8 + c2);
                v0 = __hmul2(v0, sc); v1 = __hmul2(v1, sc);
                v2 = __hmul2(v2, sc); v3 = __hmul2(v3, sc);
                qf[qh][k][0] = *(uint32_t*)&v0; qf[qh][k][1] = *(uint32_t*)&v1;
                qf[qh][k][2] = *(uint32_t*)&v2; qf[qh][k][3] = *(uint32_t*)&v3;
            }
        }
    }

    float Oa[2][8][4];
    #pragma unroll
    for (int qh = 0; qh < 2; qh++)
        #pragma unroll
        for (int nt = 0; nt < 8; nt++)
            #pragma unroll
            for (int j = 0; j < 4; j++) Oa[qh][nt][j] = 0.f;
    float mm[2][2] = {{-1e30f, -1e30f}, {-1e30f, -1e30f}};
    float ss[2][2] = {{0.f, 0.f}, {0.f, 0.f}};

    uint32_t Ks_u = smem_u32(Ks);
    uint32_t Vs_u = smem_u32(Vs);

    uint32_t koff[4];
    #pragma unroll
    for (int ntp = 0; ntp < 4; ntp++)
        koff[ntp] = (uint32_t)(((ntp*16 + (mi2 >> 1)*8 + lr2)*FVS + (mi2 & 1)*8) * 2);
    uint32_t vbase = (uint32_t)((((mi2 & 1)*8 + lr2)*FVS + (mi2 >> 1)*8) * 2);

    for (int kt = 0; kt < 4; kt++) {
        int j0 = kt * 64;
        __syncthreads();   // padf ready (kt=0) / prior tile reads done (kt>0)
        #pragma unroll
        for (int i = 0; i < 2; i++) {
            int cid = tid + i*256;
            int row = cid >> 3, kc = cid & 7;
            const __half* rowp = qkv + (size_t)(b*LL + j0 + row)*QKVD + h*DHH;
            uint32_t soff = (uint32_t)(row*FVS + kc*8) * 2;
            cp_async16(Ks_u + soff, rowp + 512 + kc*8);
            cp_async16(Vs_u + soff, rowp + 1024 + kc*8);
        }
        cp_commit();
        cp_wait<0>();
        __syncthreads();

        #pragma unroll
        for (int qh = 0; qh < 2; qh++) {
            float S[8][4];
            #pragma unroll
            for (int nt = 0; nt < 8; nt++)
                #pragma unroll
                for (int j = 0; j < 4; j++) S[nt][j] = 0.f;
            #pragma unroll
            for (int k = 0; k < 4; k++) {
                uint32_t kof = (uint32_t)(k*16*2);
                #pragma unroll
                for (int ntp = 0; ntp < 4; ntp++) {
                    uint32_t b0, b1, b2, b3;
                    ldmatrix_x4(b0, b1, b2, b3, Ks_u + koff[ntp] + kof);
                    mma_f16(S[2*ntp][0],   S[2*ntp][1],   S[2*ntp][2],   S[2*ntp][3],
                            qf[qh][k][0], qf[qh][k][1], qf[qh][k][2], qf[qh][k][3], b0, b1);
                    mma_f16(S[2*ntp+1][0], S[2*ntp+1][1], S[2*ntp+1][2], S[2*ntp+1][3],
                            qf[qh][k][0], qf[qh][k][1], qf[qh][k][2], qf[qh][k][3], b2, b3);
                }
            }
            #pragma unroll
            for (int nt = 0; nt < 8; nt++) {
                int j = j0 + nt*8 + c2;
                if (padf[j])     { S[nt][0] = -1e9f; S[nt][2] = -1e9f; }
                if (padf[j + 1]) { S[nt][1] = -1e9f; S[nt][3] = -1e9f; }
            }
            float tm0 = -1e30f, tm1 = -1e30f;
            #pragma unroll
            for (int nt = 0; nt < 8; nt++) {
                tm0 = fmaxf(tm0, fmaxf(S[nt][0], S[nt][1]));
                tm1 = fmaxf(tm1, fmaxf(S[nt][2], S[nt][3]));
            }
            tm0 = fmaxf(tm0, __shfl_xor_sync(0xffffffffu, tm0, 1));
            tm0 = fmaxf(tm0, __shfl_xor_sync(0xffffffffu, tm0, 2));
            tm1 = fmaxf(tm1, __shfl_xor_sync(0xffffffffu, tm1, 1));
            tm1 = fmaxf(tm1, __shfl_xor_sync(0xffffffffu, tm1, 2));
            float mn0 = fmaxf(mm[qh][0], tm0), mn1 = fmaxf(mm[qh][1], tm1);
            float cr0 = __expf(mm[qh][0] - mn0), cr1 = __expf(mm[qh][1] - mn1);
            float rs0 = 0.f, rs1 = 0.f;
            #pragma unroll
            for (int nt = 0; nt < 8; nt++) {
                S[nt][0] = __expf(S[nt][0] - mn0); rs0 += S[nt][0];
                S[nt][1] = __expf(S[nt][1] - mn0); rs0 += S[nt][1];
                S[nt][2] = __expf(S[nt][2] - mn1); rs1 += S[nt][2];
                S[nt][3] = __expf(S[nt][3] - mn1); rs1 += S[nt][3];
            }
            rs0 += __shfl_xor_sync(0xffffffffu, rs0, 1);
            rs0 += __shfl_xor_sync(0xffffffffu, rs0, 2);
            rs1 += __shfl_xor_sync(0xffffffffu, rs1, 1);
            rs1 += __shfl_xor_sync(0xffffffffu, rs1, 2);
            ss[qh][0] = ss[qh][0]*cr0 + rs0;  ss[qh][1] = ss[qh][1]*cr1 + rs1;
            mm[qh][0] = mn0;  mm[qh][1] = mn1;
            #pragma unroll
            for (int nt = 0; nt < 8; nt++) {
                Oa[qh][nt][0] *= cr0; Oa[qh][nt][1] *= cr0;
                Oa[qh][nt][2] *= cr1; Oa[qh][nt][3] *= cr1;
            }
            uint32_t pa[4][4];
            #pragma unroll
            for (int k = 0; k < 4; k++) {
                pa[k][0] = pack_h2(S[2*k][0],   S[2*k][1]);
                pa[k][1] = pack_h2(S[2*k][2],   S[2*k][3]);
                pa[k][2] = pack_h2(S[2*k+1][0], S[2*k+1][1]);
                pa[k][3] = pack_h2(S[2*k+1][2], S[2*k+1][3]);
            }
            #pragma unroll
            for (int k = 0; k < 4; k++) {
                uint32_t vk = vbase + (uint32_t)(k*16*FVS*2);
                #pragma unroll
                for (int ntp = 0; ntp < 4; ntp++) {
                    uint32_t b0, b1, b2, b3;
                    ldmatrix_x4_trans(b0, b1, b2, b3, Vs_u + vk + (uint32_t)(ntp*16*2));
                    mma_f16(Oa[qh][2*ntp][0],   Oa[qh][2*ntp][1],   Oa[qh][2*ntp][2],   Oa[qh][2*ntp][3],
                            pa[k][0], pa[k][1], pa[k][2], pa[k][3], b0, b1);
                    mma_f16(Oa[qh][2*ntp+1][0], Oa[qh][2*ntp+1][1], Oa[qh][2*ntp+1][2], Oa[qh][2*ntp+1][3],
                            pa[k][0], pa[k][1], pa[k][2], pa[k][3], b2, b3);
                }
            }
        }
    }

    #pragma unroll
    for (int qh = 0; qh < 2; qh++) {
        float inv0 = 1.0f / ss[qh][0], inv1 = 1.0f / ss[qh][1];
        size_t row0 = (size_t)(b*LL + qh*128 + wid*16 + r) * DD + h*DHH;
        size_t row8 = row0 + 8*DD;
        #pragma unroll
        for (int nt = 0; nt < 8; nt++) {
            *(__half2*)(ctx + row0 + nt*8 + c2) = __floats2half2_rn(Oa[qh][nt][0]*inv0, Oa[qh][nt][1]*inv0);
            *(__half2*)(ctx + row8 + nt*8 + c2) = __floats2half2_rn(Oa[qh][nt][2]*inv1, Oa[qh][nt][3]*inv1);
        }
    }
}

// ---------------- host driver ------------------------------------------------
extern "C" void kernel_launch(void* const* d_in, const int* in_sizes, int n_in,
                              void* d_out, int out_size) {
    const int*   x           = (const int*)  d_in[0];
    const float* atoms_coord = (const float*)d_in[1];
    const int*   atoms_token = (const int*)  d_in[2];
    const int*   atoms_index = (const int*)  d_in[3];
    const int*   batch_index = (const int*)  d_in[4];
    const float* emb         = (const float*)d_in[5];
    const float* coord_w     = (const float*)d_in[6];
    const float* coord_b     = (const float*)d_in[7];
    const float* rate1       = (const float*)d_in[8];
    const float* rate2       = (const float*)d_in[9];
    const float* ln1_g       = (const float*)d_in[10];
    const float* ln1_b       = (const float*)d_in[11];
    const float* wq          = (const float*)d_in[12];
    const float* bq          = (const float*)d_in[13];
    const float* wk          = (const float*)d_in[14];
    const float* bk          = (const float*)d_in[15];
    const float* wv          = (const float*)d_in[16];
    const float* bv          = (const float*)d_in[17];
    const float* wo          = (const float*)d_in[18];
    const float* bo          = (const float*)d_in[19];
    const float* ln2_g       = (const float*)d_in[20];
    const float* ln2_b       = (const float*)d_in[21];
    const float* w1          = (const float*)d_in[22];
    const float* b1          = (const float*)d_in[23];
    const float* w2          = (const float*)d_in[24];
    const float* b2          = (const float*)d_in[25];
    const float* lnf_g       = (const float*)d_in[26];
    const float* lnf_b       = (const float*)d_in[27];
    float* out = (float*)d_out;

    float *h, *bqkv;
    __half *hn, *qkv, *ctx, *ff, *wt;
    cudaGetSymbolAddress((void**)&h,    g_h);
    cudaGetSymbolAddress((void**)&hn,   g_hn);
    cudaGetSymbolAddress((void**)&qkv,  g_qkv);
    cudaGetSymbolAddress((void**)&ctx,  g_ctx);
    cudaGetSymbolAddress((void**)&ff,   g_ff);
    cudaGetSymbolAddress((void**)&wt,   g_wt);
    cudaGetSymbolAddress((void**)&bqkv, g_bqkv);

    cudaFuncSetAttribute((const void*)mma_gemm<0,0,__half>, cudaFuncAttributeMaxDynamicSharedMemorySize, SMEM_GEMM);
    cudaFuncSetAttribute((const void*)mma_gemm<0,1,float>,  cudaFuncAttributeMaxDynamicSharedMemorySize, SMEM_GEMM);
    cudaFuncSetAttribute((const void*)mma_gemm<1,0,__half>, cudaFuncAttributeMaxDynamicSharedMemorySize, SMEM_GEMM);

    // batched weight transposes (+ fp16 convert), z = layer
    dim3 tb(32, 8);
    transpose_f16_b<<<dim3(16,16,NLAYER), tb>>>(wq, wt,           DD, DD,  (size_t)DD*DD,  WT_LSTRIDE);
    transpose_f16_b<<<dim3(16,16,NLAYER), tb>>>(wk, wt + 262144,  DD, DD,  (size_t)DD*DD,  WT_LSTRIDE);
    transpose_f16_b<<<dim3(16,16,NLAYER), tb>>>(wv, wt + 524288,  DD, DD,  (size_t)DD*DD,  WT_LSTRIDE);
    transpose_f16_b<<<dim3(16,16,NLAYER), tb>>>(wo, wt + 786432,  DD, DD,  (size_t)DD*DD,  WT_LSTRIDE);
    transpose_f16_b<<<dim3(16,64,NLAYER), tb>>>(w1, wt + 1048576, DD, FFD, (size_t)DD*FFD, WT_LSTRIDE);
    transpose_f16_b<<<dim3(64,16,NLAYER), tb>>>(w2, wt + 2097152, FFD, DD, (size_t)FFD*DD, WT_LSTRIDE);
    concat_bias<<<dim3(6, NLAYER), 256>>>(bq, bk, bv, bqkv);

    embed_kernel<<<(TT*(DD/4))/256, 256>>>(x, emb, rate1, h);
    atom_kernel<<<NATOM, 128>>>(atoms_coord, atoms_token, atoms_index, batch_index,
                                emb, coord_w, coord_b, rate2, h);

    dim3 gD(DD/128, TT/128);       // (4, 512)
    dim3 gQKV(QKVD/128, TT/128);   // (12, 512)
    dim3 gF(FFD/128, TT/128);      // (16, 512)

    for (int l = 0; l < NLAYER; l++) {
        __half* base = wt + (size_t)l*WT_LSTRIDE;
        const __half* wtqkv = base;
        const __half* wto = base + 786432;
        const __half* wt1 = base + 1048576;
        const __half* wt2 = base + 2097152;

        ln_kernel<<<TT/8, 256>>>(h, hn, ln1_g + l*DD, ln1_b + l*DD);
        mma_gemm<0,0,__half><<<gQKV, 256, SMEM_GEMM>>>(DD, hn, wtqkv, bqkv + (size_t)l*QKVD,
                                                       nullptr, qkv, QKVD);
        flash_kernel<<<BB*HH, 256>>>(qkv, x, ctx);
        mma_gemm<0,1,float><<<gD, 256, SMEM_GEMM>>>(DD, ctx, wto, bo + l*DD, h, h, DD);
        ln_kernel<<<TT/8, 256>>>(h, hn, ln2_g + l*DD, ln2_b + l*DD);
        mma_gemm<1,0,__half><<<gF, 256, SMEM_GEMM>>>(DD, hn, wt1, b1 + l*FFD, nullptr, ff, FFD);
        mma_gemm<0,1,float><<<gD, 256, SMEM_GEMM>>>(FFD, ff, wt2, b2 + l*DD, h, h, DD);
    }
    lnf_kernel<<<TT/8, 256>>>(h, out, lnf_g, lnf_b);
}

// round 14
// speedup vs baseline: 1.0552x; 1.0552x over previous
#include <cuda_runtime.h>
#include <cuda_fp16.h>
#include <math.h>
#include <stdint.h>

// Problem constants
#define BB 256
#define LL 256
#define DD 512
#define HH 8
#define DHH 64
#define NLAYER 6
#define FFD 2048
#define TT (BB*LL)          // 65536 tokens
#define NATOM 32768
#define QKVD 1536

// ---------------- scratch (device globals; no allocation allowed) -----------
__device__ float  g_h  [(size_t)TT*DD];
__device__ __half g_hn [(size_t)TT*DD];
__device__ __half g_qkv[(size_t)TT*QKVD];      // 201 MB
__device__ __half g_ctx[(size_t)TT*DD];
__device__ __half g_ff [(size_t)TT*FFD];       // 268 MB
#define WT_LSTRIDE 3145728
__device__ __half g_wt [(size_t)NLAYER*WT_LSTRIDE];  // 37.7 MB
__device__ float  g_bqkv[(size_t)NLAYER*QKVD];

// ---------------- small helpers ----------------------------------------------
__device__ __forceinline__ uint32_t smem_u32(const void* p) {
    uint32_t a;
    asm("{ .reg .u64 t; cvta.to.shared.u64 t, %1; cvt.u32.u64 %0, t; }" : "=r"(a) : "l"(p));
    return a;
}
__device__ __forceinline__ void cp_async16(uint32_t dst, const void* src) {
    asm volatile("cp.async.cg.shared.global [%0], [%1], 16;" :: "r"(dst), "l"(src) : "memory");
}
__device__ __forceinline__ void cp_commit() {
    asm volatile("cp.async.commit_group;" ::: "memory");
}
template<int N>
__device__ __forceinline__ void cp_wait() {
    asm volatile("cp.async.wait_group %0;" :: "n"(N) : "memory");
}
__device__ __forceinline__ void mma_f16(float& d0, float& d1, float& d2, float& d3,
                                        uint32_t a0, uint32_t a1, uint32_t a2, uint32_t a3,
                                        uint32_t b0, uint32_t b1) {
    asm volatile(
        "mma.sync.aligned.m16n8k16.row.col.f32.f16.f16.f32 "
        "{%0,%1,%2,%3}, {%4,%5,%6,%7}, {%8,%9}, {%0,%1,%2,%3};"
        : "+f"(d0), "+f"(d1), "+f"(d2), "+f"(d3)
        : "r"(a0), "r"(a1), "r"(a2), "r"(a3), "r"(b0), "r"(b1));
}
__device__ __forceinline__ void ldmatrix_x4(uint32_t& r0, uint32_t& r1, uint32_t& r2, uint32_t& r3,
                                            uint32_t addr) {
    asm volatile("ldmatrix.sync.aligned.m8n8.x4.shared.b16 {%0,%1,%2,%3}, [%4];"
                 : "=r"(r0), "=r"(r1), "=r"(r2), "=r"(r3) : "r"(addr));
}
__device__ __forceinline__ void ldmatrix_x4_trans(uint32_t& r0, uint32_t& r1, uint32_t& r2, uint32_t& r3,
                                                  uint32_t addr) {
    asm volatile("ldmatrix.sync.aligned.m8n8.x4.trans.shared.b16 {%0,%1,%2,%3}, [%4];"
                 : "=r"(r0), "=r"(r1), "=r"(r2), "=r"(r3) : "r"(addr));
}
__device__ __forceinline__ uint32_t pack_h2(float a, float b) {
    __half2 h = __floats2half2_rn(a, b);
    return *(uint32_t*)&h;
}
// output store helpers
__device__ __forceinline__ void store_pair(float* p, float vx, float vy) {
    *(float2*)p = make_float2(vx, vy);
}
__device__ __forceinline__ void store_pair(__half* p, float vx, float vy) {
    *(__half2*)p = __floats2half2_rn(vx, vy);
}
__device__ __forceinline__ float warp_sum(float v) {
    #pragma unroll
    for (int o = 16; o; o >>= 1) v += __shfl_xor_sync(0xffffffffu, v, o);
    return v;
}

// ---------------- embedding -------------------------------------------------
__global__ void embed_kernel(const int* __restrict__ x, const float* __restrict__ emb,
                             const float* __restrict__ rate1, float* __restrict__ h) {
    int idx = blockIdx.x * blockDim.x + threadIdx.x;
    int t = idx / (DD/4);
    int c = idx % (DD/4);
    int b = t / LL, l = t % LL;
    int tok = x[l*BB + b];
    float4 e = ((const float4*)(emb + (size_t)tok*DD))[c];
    float r = rate1[0];
    ((float4*)(h + (size_t)t*DD))[c] = make_float4(r*e.x, r*e.y, r*e.z, r*e.w);
}

__global__ void atom_kernel(const float* __restrict__ coord, const int* __restrict__ atok,
                            const int* __restrict__ aidx, const int* __restrict__ bidx,
                            const float* __restrict__ emb, const float* __restrict__ cw,
                            const float* __restrict__ cb, const float* __restrict__ rate2,
                            float* __restrict__ h) {
    int a = blockIdx.x;
    int tok = atok[a];
    float c0 = coord[a*3+0], c1 = coord[a*3+1], c2 = coord[a*3+2];
    size_t row = (size_t)(bidx[a]*LL + aidx[a] + 1) * DD;
    float r = rate2[0];
    for (int i = threadIdx.x; i < DD; i += blockDim.x) {
        float val = emb[(size_t)tok*DD + i] + c0*cw[i] + c1*cw[DD+i] + c2*cw[2*DD+i] + cb[i];
        h[row + i] += r * val;
    }
}

// ---------------- warp-per-row layernorm (half out; no barriers) -------------
__global__ void __launch_bounds__(256)
ln_kernel(const float* __restrict__ in, __half* __restrict__ out,
          const float* __restrict__ g, const float* __restrict__ bt) {
    int wid = threadIdx.x >> 5, lane = threadIdx.x & 31;
    size_t row = (size_t)blockIdx.x*8 + wid;
    const float4* p = (const float4*)(in + row*DD);
    float4 v[4];
    float s = 0.f;
    #pragma unroll
    for (int k = 0; k < 4; k++) {
        v[k] = p[lane + k*32];
        s += (v[k].x + v[k].y) + (v[k].z + v[k].w);
    }
    float mean = warp_sum(s) * (1.0f/DD);
    float s2 = 0.f;
    #pragma unroll
    for (int k = 0; k < 4; k++) {
        v[k].x -= mean; v[k].y -= mean; v[k].z -= mean; v[k].w -= mean;
        s2 += (v[k].x*v[k].x + v[k].y*v[k].y) + (v[k].z*v[k].z + v[k].w*v[k].w);
    }
    float rs = rsqrtf(warp_sum(s2) * (1.0f/DD) + 1e-6f);
    const float4* gp = (const float4*)g;
    const float4* bp = (const float4*)bt;
    #pragma unroll
    for (int k = 0; k < 4; k++) {
        int idx = lane + k*32;
        float4 gv = gp[idx], bv = bp[idx];
        uint2 o2;
        o2.x = pack_h2(v[k].x*rs*gv.x + bv.x, v[k].y*rs*gv.y + bv.y);
        o2.y = pack_h2(v[k].z*rs*gv.z + bv.z, v[k].w*rs*gv.w + bv.w);
        *(uint2*)(out + row*DD + (size_t)idx*4) = o2;
    }
}

// final LN + transpose [B,L,D] -> [L,B,D], warp-per-row
__global__ void __launch_bounds__(256)
lnf_kernel(const float* __restrict__ in, float* __restrict__ out,
           const float* __restrict__ g, const float* __restrict__ bt) {
    int wid = threadIdx.x >> 5, lane = threadIdx.x & 31;
    size_t t = (size_t)blockIdx.x*8 + wid;
    int b = (int)(t / LL), l = (int)(t % LL);
    const float4* p = (const float4*)(in + t*DD);
    float4 v[4];
    float s = 0.f;
    #pragma unroll
    for (int k = 0; k < 4; k++) {
        v[k] = p[lane + k*32];
        s += (v[k].x + v[k].y) + (v[k].z + v[k].w);
    }
    float mean = warp_sum(s) * (1.0f/DD);
    float s2 = 0.f;
    #pragma unroll
    for (int k = 0; k < 4; k++) {
        v[k].x -= mean; v[k].y -= mean; v[k].z -= mean; v[k].w -= mean;
        s2 += (v[k].x*v[k].x + v[k].y*v[k].y) + (v[k].z*v[k].z + v[k].w*v[k].w);
    }
    float rs = rsqrtf(warp_sum(s2) * (1.0f/DD) + 1e-6f);
    const float4* gp = (const float4*)g;
    const float4* bp = (const float4*)bt;
    float4* op = (float4*)(out + (size_t)(l*BB + b)*DD);
    #pragma unroll
    for (int k = 0; k < 4; k++) {
        int idx = lane + k*32;
        float4 gv = gp[idx], bv = bp[idx];
        op[idx] = make_float4(v[k].x*rs*gv.x + bv.x, v[k].y*rs*gv.y + bv.y,
                              v[k].z*rs*gv.z + bv.z, v[k].w*rs*gv.w + bv.w);
    }
}

// ---------------- weight transpose + fp16 convert, batched over layers ------
__global__ void transpose_f16_b(const float* __restrict__ W, __half* __restrict__ Wt,
                                int K, int N, size_t w_stride, size_t wt_stride) {
    __shared__ float t[32][33];
    const float* Wl = W + (size_t)blockIdx.z * w_stride;
    __half* Wtl = Wt + (size_t)blockIdx.z * wt_stride;
    int k0 = blockIdx.x*32, n0 = blockIdx.y*32;
    int tx = threadIdx.x, ty = threadIdx.y;
    for (int i = ty; i < 32; i += 8)
        t[i][tx] = Wl[(size_t)(k0+i)*N + n0 + tx];
    __syncthreads();
    for (int i = ty; i < 32; i += 8)
        Wtl[(size_t)(n0+i)*K + k0 + tx] = __float2half(t[tx][i]);
}

// ---------------- concat QKV bias --------------------------------------------
__global__ void concat_bias(const float* __restrict__ bq, const float* __restrict__ bk,
                            const float* __restrict__ bv, float* __restrict__ bqkv) {
    int l = blockIdx.y;
    int i = blockIdx.x*256 + threadIdx.x;
    float v;
    if (i < 512)       v = bq[l*DD + i];
    else if (i < 1024) v = bk[l*DD + i - 512];
    else               v = bv[l*DD + i - 1024];
    bqkv[(size_t)l*QKVD + i] = v;
}

// ---------------- fp16 mma GEMM: C[M,N] = A[M,K] @ Wt[N,K]^T + bias ----------
// BM=BN=128, BK=64 halves, 256 threads = 8 warps (4 M x 2 N), warp tile 32x64.
// 3-stage cp.async pipeline; 2 CTAs/SM (3*36864*2 = 221KB <= 228KB/SM).
#define SROWH 72
#define TILEH (128*SROWH)
#define STAGEH (2*TILEH)               // A+B halves per stage
#define SMEM_GEMM (3*STAGEH*2)         // 110592 bytes

template<int RELU, int RESID, typename OutT>
__global__ void __launch_bounds__(256, 2)
mma_gemm(int K, const __half* __restrict__ A, const __half* __restrict__ Bt,
         const float* __restrict__ bias, const float* __restrict__ Res,
         OutT* __restrict__ C, int N) {
    extern __shared__ __align__(16) __half hdyn[];
    uint32_t base_u = smem_u32(hdyn);

    int tid = threadIdx.x;
    int wid = tid >> 5, lane = tid & 31;
    int warp_m = wid >> 1;
    int warp_n = wid & 1;
    int bm = blockIdx.y, bn = blockIdx.x;

    const __half* Abase = A  + (size_t)bm*128*K;
    const __half* Bbase = Bt + (size_t)bn*128*K;

    auto load_tile = [&](int buf, int c) {
        const __half* Ap = Abase + c*64;
        const __half* Bp = Bbase + c*64;
        uint32_t sa = base_u + (uint32_t)buf*STAGEH*2;
        uint32_t sb = sa + (uint32_t)TILEH*2;
        #pragma unroll
        for (int i = 0; i < 4; i++) {
            int cid = tid + i*256;
            int row = cid >> 3;
            int kc  = cid & 7;
            uint32_t soff = (uint32_t)(row*144 + kc*16);
            cp_async16(sa + soff, Ap + (size_t)row*K + kc*8);
            cp_async16(sb + soff, Bp + (size_t)row*K + kc*8);
        }
    };

    float acc[2][8][4];
    #pragma unroll
    for (int mt = 0; mt < 2; mt++)
        #pragma unroll
        for (int nt = 0; nt < 8; nt++)
            #pragma unroll
            for (int j = 0; j < 4; j++) acc[mt][nt][j] = 0.f;

    int NC = K >> 6;
    load_tile(0, 0);
    cp_commit();
    if (NC > 1) { load_tile(1, 1); cp_commit(); }

    int r = lane >> 2;      // 0..7
    int cq = lane & 3;      // 0..3
    int mi = lane >> 3, lr = lane & 7;
    uint32_t aoff[2], boff[4];
    #pragma unroll
    for (int mt = 0; mt < 2; mt++)
        aoff[mt] = (uint32_t)(((warp_m*32 + mt*16 + (mi & 1)*8 + lr)*SROWH + (mi >> 1)*8) * 2);
    #pragma unroll
    for (int ntp = 0; ntp < 4; ntp++)
        boff[ntp] = (uint32_t)(((warp_n*64 + ntp*16 + (mi >> 1)*8 + lr)*SROWH + (mi & 1)*8) * 2);

    int buf = 0;
    for (int c = 0; c < NC; c++) {
        if (c + 1 < NC) cp_wait<1>();
        else            cp_wait<0>();
        __syncthreads();

        uint32_t tA_u = base_u + (uint32_t)buf*STAGEH*2;
        uint32_t tB_u = tA_u + (uint32_t)TILEH*2;
        #pragma unroll
        for (int kk = 0; kk < 4; kk++) {
            uint32_t kof = (uint32_t)(kk*16*2);
            uint32_t af[2][4];
            ldmatrix_x4(af[0][0], af[0][1], af[0][2], af[0][3], tA_u + aoff[0] + kof);
            ldmatrix_x4(af[1][0], af[1][1], af[1][2], af[1][3], tA_u + aoff[1] + kof);
            #pragma unroll
            for (int ntp = 0; ntp < 4; ntp++) {
                uint32_t b0, b1, b2, b3;
                ldmatrix_x4(b0, b1, b2, b3, tB_u + boff[ntp] + kof);
                #pragma unroll
                for (int mt = 0; mt < 2; mt++) {
                    mma_f16(acc[mt][2*ntp][0],   acc[mt][2*ntp][1],   acc[mt][2*ntp][2],   acc[mt][2*ntp][3],
                            af[mt][0], af[mt][1], af[mt][2], af[mt][3], b0, b1);
                    mma_f16(acc[mt][2*ntp+1][0], acc[mt][2*ntp+1][1], acc[mt][2*ntp+1][2], acc[mt][2*ntp+1][3],
                            af[mt][0], af[mt][1], af[mt][2], af[mt][3], b2, b3);
                }
            }
        }
        if (c + 2 < NC) {
            int nb = buf + 2; if (nb >= 3) nb -= 3;
            load_tile(nb, c + 2);
            cp_commit();
        }
        buf++; if (buf == 3) buf = 0;
    }

    #pragma unroll
    for (int mt = 0; mt < 2; mt++) {
        size_t m0 = (size_t)bm*128 + warp_m*32 + mt*16 + r;
        #pragma unroll
        for (int nt = 0; nt < 8; nt++) {
            int n = bn*128 + warp_n*64 + nt*8 + 2*cq;
            float2 bs = *(const float2*)(bias + n);
            #pragma unroll
            for (int half_i = 0; half_i < 2; half_i++) {
                size_t m = m0 + half_i*8;
                float vx = acc[mt][nt][half_i*2 + 0] + bs.x;
                float vy = acc[mt][nt][half_i*2 + 1] + bs.y;
                if (RESID) {
                    float2 rr = *(const float2*)(Res + m*N + n);
                    vx += rr.x; vy += rr.y;
                }
                if (RELU) {
                    vx = fmaxf(vx, 0.f);
                    vy = fmaxf(vy, 0.f);
                }
                store_pair(C + m*N + n, vx, vy);
            }
        }
    }
}

// ---------------- fp16 mma flash attention (R12 version: 2 CTAs/head) --------
#define FVS 72

__global__ void __launch_bounds__(256)
flash_kernel(const __half* __restrict__ qkv, const int* __restrict__ x,
             __half* __restrict__ ctx) {
    __shared__ __align__(16) __half Ks[64*FVS];
    __shared__ __align__(16) __half Vs[64*FVS];
    __shared__ int padf[64];

    int bh = blockIdx.y, b = bh >> 3, h = bh & 7;
    int i0 = blockIdx.x * 128;
    int tid = threadIdx.x;
    int wid = tid >> 5, lane = tid & 31;
    int r = lane >> 2, c2 = (lane & 3) * 2;
    int mi2 = lane >> 3, lr2 = lane & 7;

    uint32_t qf[4][4];
    {
        const __half2 sc = __float2half2_rn(0.125f);
        size_t row0 = (size_t)(b*LL + i0 + wid*16 + r) * QKVD + h*DHH;
        #pragma unroll
        for (int k = 0; k < 4; k++) {
            __half2 v0 = *(const __half2*)(qkv + row0 + k*16 + c2);
            __half2 v1 = *(const __half2*)(qkv + row0 + 8*QKVD + k*16 + c2);
            __half2 v2 = *(const __half2*)(qkv + row0 + k*16 + 8 + c2);
            __half2 v3 = *(const __half2*)(qkv + row0 + 8*QKVD + k*16 + 8 + c2);
            v0 = __hmul2(v0, sc); v1 = __hmul2(v1, sc);
            v2 = __hmul2(v2, sc); v3 = __hmul2(v3, sc);
            qf[k][0] = *(uint32_t*)&v0; qf[k][1] = *(uint32_t*)&v1;
            qf[k][2] = *(uint32_t*)&v2; qf[k][3] = *(uint32_t*)&v3;
        }
    }

    float Oa[8][4];
    #pragma unroll
    for (int nt = 0; nt < 8; nt++)
        #pragma unroll
        for (int j = 0; j < 4; j++) Oa[nt][j] = 0.f;
    float m0 = -1e30f, m1 = -1e30f, s0 = 0.f, s1 = 0.f;

    uint32_t Ks_u = smem_u32(Ks);
    uint32_t Vs_u = smem_u32(Vs);

    uint32_t koff[4];
    #pragma unroll
    for (int ntp = 0; ntp < 4; ntp++)
        koff[ntp] = (uint32_t)(((ntp*16 + (mi2 >> 1)*8 + lr2)*FVS + (mi2 & 1)*8) * 2);
    uint32_t vbase = (uint32_t)((((mi2 & 1)*8 + lr2)*FVS + (mi2 >> 1)*8) * 2);

    for (int kt = 0; kt < 4; kt++) {
        int j0 = kt * 64;
        __syncthreads();
        #pragma unroll
        for (int i = 0; i < 2; i++) {
            int cid = tid + i*256;
            int row = cid >> 3, kc = cid & 7;
            const __half* rowp = qkv + (size_t)(b*LL + j0 + row)*QKVD + h*DHH;
            uint32_t soff = (uint32_t)(row*FVS + kc*8) * 2;
            cp_async16(Ks_u + soff, rowp + 512 + kc*8);
            cp_async16(Vs_u + soff, rowp + 1024 + kc*8);
        }
        cp_commit();
        if (tid < 64) padf[tid] = (x[(j0 + tid)*BB + b] == 0);
        cp_wait<0>();
        __syncthreads();

        float S[8][4];
        #pragma unroll
        for (int nt = 0; nt < 8; nt++)
            #pragma unroll
            for (int j = 0; j < 4; j++) S[nt][j] = 0.f;
        #pragma unroll
        for (int k = 0; k < 4; k++) {
            uint32_t kof = (uint32_t)(k*16*2);
            #pragma unroll
            for (int ntp = 0; ntp < 4; ntp++) {
                uint32_t b0, b1, b2, b3;
                ldmatrix_x4(b0, b1, b2, b3, Ks_u + koff[ntp] + kof);
                mma_f16(S[2*ntp][0],   S[2*ntp][1],   S[2*ntp][2],   S[2*ntp][3],
                        qf[k][0], qf[k][1], qf[k][2], qf[k][3], b0, b1);
                mma_f16(S[2*ntp+1][0], S[2*ntp+1][1], S[2*ntp+1][2], S[2*ntp+1][3],
                        qf[k][0], qf[k][1], qf[k][2], qf[k][3], b2, b3);
            }
        }
        #pragma unroll
        for (int nt = 0; nt < 8; nt++) {
            int j = nt*8 + c2;
            if (padf[j])     { S[nt][0] = -1e9f; S[nt][2] = -1e9f; }
            if (padf[j + 1]) { S[nt][1] = -1e9f; S[nt][3] = -1e9f; }
        }
        float tm0 = -1e30f, tm1 = -1e30f;
        #pragma unroll
        for (int nt = 0; nt < 8; nt++) {
            tm0 = fmaxf(tm0, fmaxf(S[nt][0], S[nt][1]));
            tm1 = fmaxf(tm1, fmaxf(S[nt][2], S[nt][3]));
        }
        tm0 = fmaxf(tm0, __shfl_xor_sync(0xffffffffu, tm0, 1));
        tm0 = fmaxf(tm0, __shfl_xor_sync(0xffffffffu, tm0, 2));
        tm1 = fmaxf(tm1, __shfl_xor_sync(0xffffffffu, tm1, 1));
        tm1 = fmaxf(tm1, __shfl_xor_sync(0xffffffffu, tm1, 2));
        float mn0 = fmaxf(m0, tm0), mn1 = fmaxf(m1, tm1);
        float cr0 = __expf(m0 - mn0), cr1 = __expf(m1 - mn1);
        float rs0 = 0.f, rs1 = 0.f;
        #pragma unroll
        for (int nt = 0; nt < 8; nt++) {
            S[nt][0] = __expf(S[nt][0] - mn0); rs0 += S[nt][0];
            S[nt][1] = __expf(S[nt][1] - mn0); rs0 += S[nt][1];
            S[nt][2] = __expf(S[nt][2] - mn1); rs1 += S[nt][2];
            S[nt][3] = __expf(S[nt][3] - mn1); rs1 += S[nt][3];
        }
        rs0 += __shfl_xor_sync(0xffffffffu, rs0, 1);
        rs0 += __shfl_xor_sync(0xffffffffu, rs0, 2);
        rs1 += __shfl_xor_sync(0xffffffffu, rs1, 1);
        rs1 += __shfl_xor_sync(0xffffffffu, rs1, 2);
        s0 = s0*cr0 + rs0;  s1 = s1*cr1 + rs1;
        m0 = mn0;  m1 = mn1;
        #pragma unroll
        for (int nt = 0; nt < 8; nt++) {
            Oa[nt][0] *= cr0; Oa[nt][1] *= cr0;
            Oa[nt][2] *= cr1; Oa[nt][3] *= cr1;
        }
        uint32_t pa[4][4];
        #pragma unroll
        for (int k = 0; k < 4; k++) {
            pa[k][0] = pack_h2(S[2*k][0],   S[2*k][1]);
            pa[k][1] = pack_h2(S[2*k][2],   S[2*k][3]);
            pa[k][2] = pack_h2(S[2*k+1][0], S[2*k+1][1]);
            pa[k][3] = pack_h2(S[2*k+1][2], S[2*k+1][3]);
        }
        #pragma unroll
        for (int k = 0; k < 4; k++) {
            uint32_t vk = vbase + (uint32_t)(k*16*FVS*2);
            #pragma unroll
            for (int ntp = 0; ntp < 4; ntp++) {
                uint32_t b0, b1, b2, b3;
                ldmatrix_x4_trans(b0, b1, b2, b3, Vs_u + vk + (uint32_t)(ntp*16*2));
                mma_f16(Oa[2*ntp][0],   Oa[2*ntp][1],   Oa[2*ntp][2],   Oa[2*ntp][3],
                        pa[k][0], pa[k][1], pa[k][2], pa[k][3], b0, b1);
                mma_f16(Oa[2*ntp+1][0], Oa[2*ntp+1][1], Oa[2*ntp+1][2], Oa[2*ntp+1][3],
                        pa[k][0], pa[k][1], pa[k][2], pa[k][3], b2, b3);
            }
        }
    }

    float inv0 = 1.0f / s0, inv1 = 1.0f / s1;
    size_t row0 = (size_t)(b*LL + i0 + wid*16 + r) * DD + h*DHH;
    size_t row8 = row0 + 8*DD;
    #pragma unroll
    for (int nt = 0; nt < 8; nt++) {
        *(__half2*)(ctx + row0 + nt*8 + c2) = __floats2half2_rn(Oa[nt][0]*inv0, Oa[nt][1]*inv0);
        *(__half2*)(ctx + row8 + nt*8 + c2) = __floats2half2_rn(Oa[nt][2]*inv1, Oa[nt][3]*inv1);
    }
}

// ---------------- host driver ------------------------------------------------
extern "C" void kernel_launch(void* const* d_in, const int* in_sizes, int n_in,
                              void* d_out, int out_size) {
    const int*   x           = (const int*)  d_in[0];
    const float* atoms_coord = (const float*)d_in[1];
    const int*   atoms_token = (const int*)  d_in[2];
    const int*   atoms_index = (const int*)  d_in[3];
    const int*   batch_index = (const int*)  d_in[4];
    const float* emb         = (const float*)d_in[5];
    const float* coord_w     = (const float*)d_in[6];
    const float* coord_b     = (const float*)d_in[7];
    const float* rate1       = (const float*)d_in[8];
    const float* rate2       = (const float*)d_in[9];
    const float* ln1_g       = (const float*)d_in[10];
    const float* ln1_b       = (const float*)d_in[11];
    const float* wq          = (const float*)d_in[12];
    const float* bq          = (const float*)d_in[13];
    const float* wk          = (const float*)d_in[14];
    const float* bk          = (const float*)d_in[15];
    const float* wv          = (const float*)d_in[16];
    const float* bv          = (const float*)d_in[17];
    const float* wo          = (const float*)d_in[18];
    const float* bo          = (const float*)d_in[19];
    const float* ln2_g       = (const float*)d_in[20];
    const float* ln2_b       = (const float*)d_in[21];
    const float* w1          = (const float*)d_in[22];
    const float* b1          = (const float*)d_in[23];
    const float* w2          = (const float*)d_in[24];
    const float* b2          = (const float*)d_in[25];
    const float* lnf_g       = (const float*)d_in[26];
    const float* lnf_b       = (const float*)d_in[27];
    float* out = (float*)d_out;

    float *h, *bqkv;
    __half *hn, *qkv, *ctx, *ff, *wt;
    cudaGetSymbolAddress((void**)&h,    g_h);
    cudaGetSymbolAddress((void**)&hn,   g_hn);
    cudaGetSymbolAddress((void**)&qkv,  g_qkv);
    cudaGetSymbolAddress((void**)&ctx,  g_ctx);
    cudaGetSymbolAddress((void**)&ff,   g_ff);
    cudaGetSymbolAddress((void**)&wt,   g_wt);
    cudaGetSymbolAddress((void**)&bqkv, g_bqkv);

    cudaFuncSetAttribute((const void*)mma_gemm<0,0,__half>, cudaFuncAttributeMaxDynamicSharedMemorySize, SMEM_GEMM);
    cudaFuncSetAttribute((const void*)mma_gemm<0,1,float>,  cudaFuncAttributeMaxDynamicSharedMemorySize, SMEM_GEMM);
    cudaFuncSetAttribute((const void*)mma_gemm<1,0,__half>, cudaFuncAttributeMaxDynamicSharedMemorySize, SMEM_GEMM);

    // batched weight transposes (+ fp16 convert), z = layer
    dim3 tb(32, 8);
    transpose_f16_b<<<dim3(16,16,NLAYER), tb>>>(wq, wt,           DD, DD,  (size_t)DD*DD,  WT_LSTRIDE);
    transpose_f16_b<<<dim3(16,16,NLAYER), tb>>>(wk, wt + 262144,  DD, DD,  (size_t)DD*DD,  WT_LSTRIDE);
    transpose_f16_b<<<dim3(16,16,NLAYER), tb>>>(wv, wt + 524288,  DD, DD,  (size_t)DD*DD,  WT_LSTRIDE);
    transpose_f16_b<<<dim3(16,16,NLAYER), tb>>>(wo, wt + 786432,  DD, DD,  (size_t)DD*DD,  WT_LSTRIDE);
    transpose_f16_b<<<dim3(16,64,NLAYER), tb>>>(w1, wt + 1048576, DD, FFD, (size_t)DD*FFD, WT_LSTRIDE);
    transpose_f16_b<<<dim3(64,16,NLAYER), tb>>>(w2, wt + 2097152, FFD, DD, (size_t)FFD*DD, WT_LSTRIDE);
    concat_bias<<<dim3(6, NLAYER), 256>>>(bq, bk, bv, bqkv);

    embed_kernel<<<(TT*(DD/4))/256, 256>>>(x, emb, rate1, h);
    atom_kernel<<<NATOM, 128>>>(atoms_coord, atoms_token, atoms_index, batch_index,
                                emb, coord_w, coord_b, rate2, h);

    dim3 gD(DD/128, TT/128);       // (4, 512)
    dim3 gQKV(QKVD/128, TT/128);   // (12, 512)
    dim3 gF(FFD/128, TT/128);      // (16, 512)
    dim3 gFA(LL/128, BB*HH);       // (2, 2048)

    for (int l = 0; l < NLAYER; l++) {
        __half* base = wt + (size_t)l*WT_LSTRIDE;
        const __half* wtqkv = base;
        const __half* wto = base + 786432;
        const __half* wt1 = base + 1048576;
        const __half* wt2 = base + 2097152;

        ln_kernel<<<TT/8, 256>>>(h, hn, ln1_g + l*DD, ln1_b + l*DD);
        mma_gemm<0,0,__half><<<gQKV, 256, SMEM_GEMM>>>(DD, hn, wtqkv, bqkv + (size_t)l*QKVD,
                                                       nullptr, qkv, QKVD);
        flash_kernel<<<gFA, 256>>>(qkv, x, ctx);
        mma_gemm<0,1,float><<<gD, 256, SMEM_GEMM>>>(DD, ctx, wto, bo + l*DD, h, h, DD);
        ln_kernel<<<TT/8, 256>>>(h, hn, ln2_g + l*DD, ln2_b + l*DD);
        mma_gemm<1,0,__half><<<gF, 256, SMEM_GEMM>>>(DD, hn, wt1, b1 + l*FFD, nullptr, ff, FFD);
        mma_gemm<0,1,float><<<gD, 256, SMEM_GEMM>>>(FFD, ff, wt2, b2 + l*DD, h, h, DD);
    }
    lnf_kernel<<<TT/8, 256>>>(h, out, lnf_g, lnf_b);
}

// round 16
// speedup vs baseline: 1.0721x; 1.0160x over previous
#include <cuda_runtime.h>
#include <cuda_fp16.h>
#include <math.h>
#include <stdint.h>

// Problem constants
#define BB 256
#define LL 256
#define DD 512
#define HH 8
#define DHH 64
#define NLAYER 6
#define FFD 2048
#define TT (BB*LL)          // 65536 tokens
#define NATOM 32768
#define QKVD 1536

// ---------------- scratch (device globals; no allocation allowed) -----------
__device__ float  g_h  [(size_t)TT*DD];
__device__ __half g_hn [(size_t)TT*DD];
__device__ __half g_qkv[(size_t)TT*QKVD];      // 201 MB
__device__ __half g_ctx[(size_t)TT*DD];
__device__ __half g_ff [(size_t)TT*FFD];       // 268 MB
#define WT_LSTRIDE 3145728
__device__ __half g_wt [(size_t)NLAYER*WT_LSTRIDE];  // 37.7 MB
__device__ float  g_bqkv[(size_t)NLAYER*QKVD];

// ---------------- small helpers ----------------------------------------------
__device__ __forceinline__ uint32_t smem_u32(const void* p) {
    uint32_t a;
    asm("{ .reg .u64 t; cvta.to.shared.u64 t, %1; cvt.u32.u64 %0, t; }" : "=r"(a) : "l"(p));
    return a;
}
__device__ __forceinline__ void cp_async16(uint32_t dst, const void* src) {
    asm volatile("cp.async.cg.shared.global [%0], [%1], 16;" :: "r"(dst), "l"(src) : "memory");
}
__device__ __forceinline__ void cp_commit() {
    asm volatile("cp.async.commit_group;" ::: "memory");
}
template<int N>
__device__ __forceinline__ void cp_wait() {
    asm volatile("cp.async.wait_group %0;" :: "n"(N) : "memory");
}
__device__ __forceinline__ void mma_f16(float& d0, float& d1, float& d2, float& d3,
                                        uint32_t a0, uint32_t a1, uint32_t a2, uint32_t a3,
                                        uint32_t b0, uint32_t b1) {
    asm volatile(
        "mma.sync.aligned.m16n8k16.row.col.f32.f16.f16.f32 "
        "{%0,%1,%2,%3}, {%4,%5,%6,%7}, {%8,%9}, {%0,%1,%2,%3};"
        : "+f"(d0), "+f"(d1), "+f"(d2), "+f"(d3)
        : "r"(a0), "r"(a1), "r"(a2), "r"(a3), "r"(b0), "r"(b1));
}
__device__ __forceinline__ void ldmatrix_x4(uint32_t& r0, uint32_t& r1, uint32_t& r2, uint32_t& r3,
                                            uint32_t addr) {
    asm volatile("ldmatrix.sync.aligned.m8n8.x4.shared.b16 {%0,%1,%2,%3}, [%4];"
                 : "=r"(r0), "=r"(r1), "=r"(r2), "=r"(r3) : "r"(addr));
}
__device__ __forceinline__ void ldmatrix_x4_trans(uint32_t& r0, uint32_t& r1, uint32_t& r2, uint32_t& r3,
                                                  uint32_t addr) {
    asm volatile("ldmatrix.sync.aligned.m8n8.x4.trans.shared.b16 {%0,%1,%2,%3}, [%4];"
                 : "=r"(r0), "=r"(r1), "=r"(r2), "=r"(r3) : "r"(addr));
}
__device__ __forceinline__ uint32_t pack_h2(float a, float b) {
    __half2 h = __floats2half2_rn(a, b);
    return *(uint32_t*)&h;
}
// output store helpers
__device__ __forceinline__ void store_pair(float* p, float vx, float vy) {
    *(float2*)p = make_float2(vx, vy);
}
__device__ __forceinline__ void store_pair(__half* p, float vx, float vy) {
    *(__half2*)p = __floats2half2_rn(vx, vy);
}
__device__ __forceinline__ float warp_sum(float v) {
    #pragma unroll
    for (int o = 16; o; o >>= 1) v += __shfl_xor_sync(0xffffffffu, v, o);
    return v;
}

// ---------------- embedding -------------------------------------------------
__global__ void embed_kernel(const int* __restrict__ x, const float* __restrict__ emb,
                             const float* __restrict__ rate1, float* __restrict__ h) {
    int idx = blockIdx.x * blockDim.x + threadIdx.x;
    int t = idx / (DD/4);
    int c = idx % (DD/4);
    int b = t / LL, l = t % LL;
    int tok = x[l*BB + b];
    float4 e = ((const float4*)(emb + (size_t)tok*DD))[c];
    float r = rate1[0];
    ((float4*)(h + (size_t)t*DD))[c] = make_float4(r*e.x, r*e.y, r*e.z, r*e.w);
}

__global__ void atom_kernel(const float* __restrict__ coord, const int* __restrict__ atok,
                            const int* __restrict__ aidx, const int* __restrict__ bidx,
                            const float* __restrict__ emb, const float* __restrict__ cw,
                            const float* __restrict__ cb, const float* __restrict__ rate2,
                            float* __restrict__ h) {
    int a = blockIdx.x;
    int tok = atok[a];
    float c0 = coord[a*3+0], c1 = coord[a*3+1], c2 = coord[a*3+2];
    size_t row = (size_t)(bidx[a]*LL + aidx[a] + 1) * DD;
    float r = rate2[0];
    for (int i = threadIdx.x; i < DD; i += blockDim.x) {
        float val = emb[(size_t)tok*DD + i] + c0*cw[i] + c1*cw[DD+i] + c2*cw[2*DD+i] + cb[i];
        h[row + i] += r * val;
    }
}

// ---------------- warp-per-row layernorm (half out; no barriers) -------------
__global__ void __launch_bounds__(256)
ln_kernel(const float* __restrict__ in, __half* __restrict__ out,
          const float* __restrict__ g, const float* __restrict__ bt) {
    int wid = threadIdx.x >> 5, lane = threadIdx.x & 31;
    size_t row = (size_t)blockIdx.x*8 + wid;
    const float4* p = (const float4*)(in + row*DD);
    float4 v[4];
    float s = 0.f;
    #pragma unroll
    for (int k = 0; k < 4; k++) {
        v[k] = p[lane + k*32];
        s += (v[k].x + v[k].y) + (v[k].z + v[k].w);
    }
    float mean = warp_sum(s) * (1.0f/DD);
    float s2 = 0.f;
    #pragma unroll
    for (int k = 0; k < 4; k++) {
        v[k].x -= mean; v[k].y -= mean; v[k].z -= mean; v[k].w -= mean;
        s2 += (v[k].x*v[k].x + v[k].y*v[k].y) + (v[k].z*v[k].z + v[k].w*v[k].w);
    }
    float rs = rsqrtf(warp_sum(s2) * (1.0f/DD) + 1e-6f);
    const float4* gp = (const float4*)g;
    const float4* bp = (const float4*)bt;
    #pragma unroll
    for (int k = 0; k < 4; k++) {
        int idx = lane + k*32;
        float4 gv = gp[idx], bv = bp[idx];
        uint2 o2;
        o2.x = pack_h2(v[k].x*rs*gv.x + bv.x, v[k].y*rs*gv.y + bv.y);
        o2.y = pack_h2(v[k].z*rs*gv.z + bv.z, v[k].w*rs*gv.w + bv.w);
        *(uint2*)(out + row*DD + (size_t)idx*4) = o2;
    }
}

// final LN + transpose [B,L,D] -> [L,B,D], warp-per-row
__global__ void __launch_bounds__(256)
lnf_kernel(const float* __restrict__ in, float* __restrict__ out,
           const float* __restrict__ g, const float* __restrict__ bt) {
    int wid = threadIdx.x >> 5, lane = threadIdx.x & 31;
    size_t t = (size_t)blockIdx.x*8 + wid;
    int b = (int)(t / LL), l = (int)(t % LL);
    const float4* p = (const float4*)(in + t*DD);
    float4 v[4];
    float s = 0.f;
    #pragma unroll
    for (int k = 0; k < 4; k++) {
        v[k] = p[lane + k*32];
        s += (v[k].x + v[k].y) + (v[k].z + v[k].w);
    }
    float mean = warp_sum(s) * (1.0f/DD);
    float s2 = 0.f;
    #pragma unroll
    for (int k = 0; k < 4; k++) {
        v[k].x -= mean; v[k].y -= mean; v[k].z -= mean; v[k].w -= mean;
        s2 += (v[k].x*v[k].x + v[k].y*v[k].y) + (v[k].z*v[k].z + v[k].w*v[k].w);
    }
    float rs = rsqrtf(warp_sum(s2) * (1.0f/DD) + 1e-6f);
    const float4* gp = (const float4*)g;
    const float4* bp = (const float4*)bt;
    float4* op = (float4*)(out + (size_t)(l*BB + b)*DD);
    #pragma unroll
    for (int k = 0; k < 4; k++) {
        int idx = lane + k*32;
        float4 gv = gp[idx], bv = bp[idx];
        op[idx] = make_float4(v[k].x*rs*gv.x + bv.x, v[k].y*rs*gv.y + bv.y,
                              v[k].z*rs*gv.z + bv.z, v[k].w*rs*gv.w + bv.w);
    }
}

// ---------------- weight transpose + fp16 convert, batched over layers ------
__global__ void transpose_f16_b(const float* __restrict__ W, __half* __restrict__ Wt,
                                int K, int N, size_t w_stride, size_t wt_stride) {
    __shared__ float t[32][33];
    const float* Wl = W + (size_t)blockIdx.z * w_stride;
    __half* Wtl = Wt + (size_t)blockIdx.z * wt_stride;
    int k0 = blockIdx.x*32, n0 = blockIdx.y*32;
    int tx = threadIdx.x, ty = threadIdx.y;
    for (int i = ty; i < 32; i += 8)
        t[i][tx] = Wl[(size_t)(k0+i)*N + n0 + tx];
    __syncthreads();
    for (int i = ty; i < 32; i += 8)
        Wtl[(size_t)(n0+i)*K + k0 + tx] = __float2half(t[tx][i]);
}

// ---------------- concat QKV bias --------------------------------------------
__global__ void concat_bias(const float* __restrict__ bq, const float* __restrict__ bk,
                            const float* __restrict__ bv, float* __restrict__ bqkv) {
    int l = blockIdx.y;
    int i = blockIdx.x*256 + threadIdx.x;
    float v;
    if (i < 512)       v = bq[l*DD + i];
    else if (i < 1024) v = bk[l*DD + i - 512];
    else               v = bv[l*DD + i - 1024];
    bqkv[(size_t)l*QKVD + i] = v;
}

// ---------------- fp16 mma GEMM: C[M,N] = A[M,K] @ Wt[N,K]^T + bias ----------
// BM=BN=128, BK=64 halves, 256 threads = 8 warps (4 M x 2 N), warp tile 32x64.
// 3-stage cp.async pipeline; 2 CTAs/SM (3*36864*2 = 221KB <= 228KB/SM).
#define SROWH 72
#define TILEH (128*SROWH)
#define STAGEH (2*TILEH)               // A+B halves per stage
#define SMEM_GEMM (3*STAGEH*2)         // 110592 bytes

template<int RELU, int RESID, typename OutT>
__global__ void __launch_bounds__(256, 2)
mma_gemm(int K, const __half* __restrict__ A, const __half* __restrict__ Bt,
         const float* __restrict__ bias, const float* __restrict__ Res,
         OutT* __restrict__ C, int N) {
    extern __shared__ __align__(16) __half hdyn[];
    uint32_t base_u = smem_u32(hdyn);

    int tid = threadIdx.x;
    int wid = tid >> 5, lane = tid & 31;
    int warp_m = wid >> 1;
    int warp_n = wid & 1;
    int bm = blockIdx.y, bn = blockIdx.x;

    const __half* Abase = A  + (size_t)bm*128*K;
    const __half* Bbase = Bt + (size_t)bn*128*K;

    auto load_tile = [&](int buf, int c) {
        const __half* Ap = Abase + c*64;
        const __half* Bp = Bbase + c*64;
        uint32_t sa = base_u + (uint32_t)buf*STAGEH*2;
        uint32_t sb = sa + (uint32_t)TILEH*2;
        #pragma unroll
        for (int i = 0; i < 4; i++) {
            int cid = tid + i*256;
            int row = cid >> 3;
            int kc  = cid & 7;
            uint32_t soff = (uint32_t)(row*144 + kc*16);
            cp_async16(sa + soff, Ap + (size_t)row*K + kc*8);
            cp_async16(sb + soff, Bp + (size_t)row*K + kc*8);
        }
    };

    float acc[2][8][4];
    #pragma unroll
    for (int mt = 0; mt < 2; mt++)
        #pragma unroll
        for (int nt = 0; nt < 8; nt++)
            #pragma unroll
            for (int j = 0; j < 4; j++) acc[mt][nt][j] = 0.f;

    int NC = K >> 6;
    load_tile(0, 0);
    cp_commit();
    if (NC > 1) { load_tile(1, 1); cp_commit(); }

    int r = lane >> 2;      // 0..7
    int cq = lane & 3;      // 0..3
    int mi = lane >> 3, lr = lane & 7;
    uint32_t aoff[2], boff[4];
    #pragma unroll
    for (int mt = 0; mt < 2; mt++)
        aoff[mt] = (uint32_t)(((warp_m*32 + mt*16 + (mi & 1)*8 + lr)*SROWH + (mi >> 1)*8) * 2);
    #pragma unroll
    for (int ntp = 0; ntp < 4; ntp++)
        boff[ntp] = (uint32_t)(((warp_n*64 + ntp*16 + (mi >> 1)*8 + lr)*SROWH + (mi & 1)*8) * 2);

    int buf = 0;
    for (int c = 0; c < NC; c++) {
        if (c + 1 < NC) cp_wait<1>();
        else            cp_wait<0>();
        __syncthreads();

        uint32_t tA_u = base_u + (uint32_t)buf*STAGEH*2;
        uint32_t tB_u = tA_u + (uint32_t)TILEH*2;
        #pragma unroll
        for (int kk = 0; kk < 4; kk++) {
            uint32_t kof = (uint32_t)(kk*16*2);
            uint32_t af[2][4];
            ldmatrix_x4(af[0][0], af[0][1], af[0][2], af[0][3], tA_u + aoff[0] + kof);
            ldmatrix_x4(af[1][0], af[1][1], af[1][2], af[1][3], tA_u + aoff[1] + kof);
            #pragma unroll
            for (int ntp = 0; ntp < 4; ntp++) {
                uint32_t b0, b1, b2, b3;
                ldmatrix_x4(b0, b1, b2, b3, tB_u + boff[ntp] + kof);
                #pragma unroll
                for (int mt = 0; mt < 2; mt++) {
                    mma_f16(acc[mt][2*ntp][0],   acc[mt][2*ntp][1],   acc[mt][2*ntp][2],   acc[mt][2*ntp][3],
                            af[mt][0], af[mt][1], af[mt][2], af[mt][3], b0, b1);
                    mma_f16(acc[mt][2*ntp+1][0], acc[mt][2*ntp+1][1], acc[mt][2*ntp+1][2], acc[mt][2*ntp+1][3],
                            af[mt][0], af[mt][1], af[mt][2], af[mt][3], b2, b3);
                }
            }
        }
        if (c + 2 < NC) {
            int nb = buf + 2; if (nb >= 3) nb -= 3;
            load_tile(nb, c + 2);
            cp_commit();
        }
        buf++; if (buf == 3) buf = 0;
    }

    #pragma unroll
    for (int mt = 0; mt < 2; mt++) {
        size_t m0 = (size_t)bm*128 + warp_m*32 + mt*16 + r;
        #pragma unroll
        for (int nt = 0; nt < 8; nt++) {
            int n = bn*128 + warp_n*64 + nt*8 + 2*cq;
            float2 bs = *(const float2*)(bias + n);
            #pragma unroll
            for (int half_i = 0; half_i < 2; half_i++) {
                size_t m = m0 + half_i*8;
                float vx = acc[mt][nt][half_i*2 + 0] + bs.x;
                float vy = acc[mt][nt][half_i*2 + 1] + bs.y;
                if (RESID) {
                    float2 rr = *(const float2*)(Res + m*N + n);
                    vx += rr.x; vy += rr.y;
                }
                if (RELU) {
                    vx = fmaxf(vx, 0.f);
                    vy = fmaxf(vy, 0.f);
                }
                store_pair(C + m*N + n, vx, vy);
            }
        }
    }
}

// ---------------- fp16 mma flash attention (3-buffer K/V ring) ---------------
// Buffer (kt+2)%3 was last read in iteration kt-1, which every thread exited
// through the barrier at the top of iteration kt -> prefetch is race-free.
#define FVS 72
#define FTILEH (64*FVS)

__global__ void __launch_bounds__(256)
flash_kernel(const __half* __restrict__ qkv, const int* __restrict__ x,
             __half* __restrict__ ctx) {
    __shared__ __align__(16) __half Ks[3*FTILEH];
    __shared__ __align__(16) __half Vs[3*FTILEH];
    __shared__ int padf[256];

    int bh = blockIdx.y, b = bh >> 3, h = bh & 7;
    int i0 = blockIdx.x * 128;
    int tid = threadIdx.x;
    int wid = tid >> 5, lane = tid & 31;
    int r = lane >> 2, c2 = (lane & 3) * 2;
    int mi2 = lane >> 3, lr2 = lane & 7;

    uint32_t Ks_u = smem_u32(Ks);
    uint32_t Vs_u = smem_u32(Vs);

    auto load_kv = [&](int buf, int kt) {
        int j0 = kt * 64;
        uint32_t kb = Ks_u + (uint32_t)buf*FTILEH*2;
        uint32_t vb = Vs_u + (uint32_t)buf*FTILEH*2;
        #pragma unroll
        for (int i = 0; i < 2; i++) {
            int cid = tid + i*256;
            int row = cid >> 3, kc = cid & 7;
            const __half* rowp = qkv + (size_t)(b*LL + j0 + row)*QKVD + h*DHH;
            uint32_t soff = (uint32_t)(row*FVS + kc*8) * 2;
            cp_async16(kb + soff, rowp + 512 + kc*8);
            cp_async16(vb + soff, rowp + 1024 + kc*8);
        }
    };

    // kick off tile 0 ASAP
    load_kv(0, 0);
    cp_commit();
    // all 256 pad flags once
    padf[tid] = (x[tid*BB + b] == 0);

    uint32_t qf[4][4];
    {
        const __half2 sc = __float2half2_rn(0.125f);
        size_t row0 = (size_t)(b*LL + i0 + wid*16 + r) * QKVD + h*DHH;
        #pragma unroll
        for (int k = 0; k < 4; k++) {
            __half2 v0 = *(const __half2*)(qkv + row0 + k*16 + c2);
            __half2 v1 = *(const __half2*)(qkv + row0 + 8*QKVD + k*16 + c2);
            __half2 v2 = *(const __half2*)(qkv + row0 + k*16 + 8 + c2);
            __half2 v3 = *(const __half2*)(qkv + row0 + 8*QKVD + k*16 + 8 + c2);
            v0 = __hmul2(v0, sc); v1 = __hmul2(v1, sc);
            v2 = __hmul2(v2, sc); v3 = __hmul2(v3, sc);
            qf[k][0] = *(uint32_t*)&v0; qf[k][1] = *(uint32_t*)&v1;
            qf[k][2] = *(uint32_t*)&v2; qf[k][3] = *(uint32_t*)&v3;
        }
    }
    load_kv(1, 1);
    cp_commit();

    float Oa[8][4];
    #pragma unroll
    for (int nt = 0; nt < 8; nt++)
        #pragma unroll
        for (int j = 0; j < 4; j++) Oa[nt][j] = 0.f;
    float m0 = -1e30f, m1 = -1e30f, s0 = 0.f, s1 = 0.f;

    uint32_t koff[4];
    #pragma unroll
    for (int ntp = 0; ntp < 4; ntp++)
        koff[ntp] = (uint32_t)(((ntp*16 + (mi2 >> 1)*8 + lr2)*FVS + (mi2 & 1)*8) * 2);
    uint32_t vbase = (uint32_t)((((mi2 & 1)*8 + lr2)*FVS + (mi2 >> 1)*8) * 2);

    int buf = 0;
    for (int kt = 0; kt < 4; kt++) {
        int j0 = kt * 64;
        if (kt + 1 < 4) cp_wait<1>();
        else            cp_wait<0>();
        __syncthreads();

        uint32_t kb = Ks_u + (uint32_t)buf*FTILEH*2;
        uint32_t vb = Vs_u + (uint32_t)buf*FTILEH*2;

        float S[8][4];
        #pragma unroll
        for (int nt = 0; nt < 8; nt++)
            #pragma unroll
            for (int j = 0; j < 4; j++) S[nt][j] = 0.f;
        #pragma unroll
        for (int k = 0; k < 4; k++) {
            uint32_t kof = (uint32_t)(k*16*2);
            #pragma unroll
            for (int ntp = 0; ntp < 4; ntp++) {
                uint32_t b0, b1, b2, b3;
                ldmatrix_x4(b0, b1, b2, b3, kb + koff[ntp] + kof);
                mma_f16(S[2*ntp][0],   S[2*ntp][1],   S[2*ntp][2],   S[2*ntp][3],
                        qf[k][0], qf[k][1], qf[k][2], qf[k][3], b0, b1);
                mma_f16(S[2*ntp+1][0], S[2*ntp+1][1], S[2*ntp+1][2], S[2*ntp+1][3],
                        qf[k][0], qf[k][1], qf[k][2], qf[k][3], b2, b3);
            }
        }
        #pragma unroll
        for (int nt = 0; nt < 8; nt++) {
            int j = j0 + nt*8 + c2;
            if (padf[j])     { S[nt][0] = -1e9f; S[nt][2] = -1e9f; }
            if (padf[j + 1]) { S[nt][1] = -1e9f; S[nt][3] = -1e9f; }
        }
        float tm0 = -1e30f, tm1 = -1e30f;
        #pragma unroll
        for (int nt = 0; nt < 8; nt++) {
            tm0 = fmaxf(tm0, fmaxf(S[nt][0], S[nt][1]));
            tm1 = fmaxf(tm1, fmaxf(S[nt][2], S[nt][3]));
        }
        tm0 = fmaxf(tm0, __shfl_xor_sync(0xffffffffu, tm0, 1));
        tm0 = fmaxf(tm0, __shfl_xor_sync(0xffffffffu, tm0, 2));
        tm1 = fmaxf(tm1, __shfl_xor_sync(0xffffffffu, tm1, 1));
        tm1 = fmaxf(tm1, __shfl_xor_sync(0xffffffffu, tm1, 2));
        float mn0 = fmaxf(m0, tm0), mn1 = fmaxf(m1, tm1);
        float cr0 = __expf(m0 - mn0), cr1 = __expf(m1 - mn1);
        float rs0 = 0.f, rs1 = 0.f;
        #pragma unroll
        for (int nt = 0; nt < 8; nt++) {
            S[nt][0] = __expf(S[nt][0] - mn0); rs0 += S[nt][0];
            S[nt][1] = __expf(S[nt][1] - mn0); rs0 += S[nt][1];
            S[nt][2] = __expf(S[nt][2] - mn1); rs1 += S[nt][2];
            S[nt][3] = __expf(S[nt][3] - mn1); rs1 += S[nt][3];
        }
        rs0 += __shfl_xor_sync(0xffffffffu, rs0, 1);
        rs0 += __shfl_xor_sync(0xffffffffu, rs0, 2);
        rs1 += __shfl_xor_sync(0xffffffffu, rs1, 1);
        rs1 += __shfl_xor_sync(0xffffffffu, rs1, 2);
        s0 = s0*cr0 + rs0;  s1 = s1*cr1 + rs1;
        m0 = mn0;  m1 = mn1;
        #pragma unroll
        for (int nt = 0; nt < 8; nt++) {
            Oa[nt][0] *= cr0; Oa[nt][1] *= cr0;
            Oa[nt][2] *= cr1; Oa[nt][3] *= cr1;
        }
        uint32_t pa[4][4];
        #pragma unroll
        for (int k = 0; k < 4; k++) {
            pa[k][0] = pack_h2(S[2*k][0],   S[2*k][1]);
            pa[k][1] = pack_h2(S[2*k][2],   S[2*k][3]);
            pa[k][2] = pack_h2(S[2*k+1][0], S[2*k+1][1]);
            pa[k][3] = pack_h2(S[2*k+1][2], S[2*k+1][3]);
        }
        #pragma unroll
        for (int k = 0; k < 4; k++) {
            uint32_t vk = vbase + (uint32_t)(k*16*FVS*2);
            #pragma unroll
            for (int ntp = 0; ntp < 4; ntp++) {
                uint32_t b0, b1, b2, b3;
                ldmatrix_x4_trans(b0, b1, b2, b3, vb + vk + (uint32_t)(ntp*16*2));
                mma_f16(Oa[2*ntp][0],   Oa[2*ntp][1],   Oa[2*ntp][2],   Oa[2*ntp][3],
                        pa[k][0], pa[k][1], pa[k][2], pa[k][3], b0, b1);
                mma_f16(Oa[2*ntp+1][0], Oa[2*ntp+1][1], Oa[2*ntp+1][2], Oa[2*ntp+1][3],
                        pa[k][0], pa[k][1], pa[k][2], pa[k][3], b2, b3);
            }
        }
        if (kt + 2 < 4) {
            int nb = buf + 2; if (nb >= 3) nb -= 3;
            load_kv(nb, kt + 2);
            cp_commit();
        }
        buf++; if (buf == 3) buf = 0;
    }

    float inv0 = 1.0f / s0, inv1 = 1.0f / s1;
    size_t row0 = (size_t)(b*LL + i0 + wid*16 + r) * DD + h*DHH;
    size_t row8 = row0 + 8*DD;
    #pragma unroll
    for (int nt = 0; nt < 8; nt++) {
        *(__half2*)(ctx + row0 + nt*8 + c2) = __floats2half2_rn(Oa[nt][0]*inv0, Oa[nt][1]*inv0);
        *(__half2*)(ctx + row8 + nt*8 + c2) = __floats2half2_rn(Oa[nt][2]*inv1, Oa[nt][3]*inv1);
    }
}

// ---------------- host driver ------------------------------------------------
extern "C" void kernel_launch(void* const* d_in, const int* in_sizes, int n_in,
                              void* d_out, int out_size) {
    const int*   x           = (const int*)  d_in[0];
    const float* atoms_coord = (const float*)d_in[1];
    const int*   atoms_token = (const int*)  d_in[2];
    const int*   atoms_index = (const int*)  d_in[3];
    const int*   batch_index = (const int*)  d_in[4];
    const float* emb         = (const float*)d_in[5];
    const float* coord_w     = (const float*)d_in[6];
    const float* coord_b     = (const float*)d_in[7];
    const float* rate1       = (const float*)d_in[8];
    const float* rate2       = (const float*)d_in[9];
    const float* ln1_g       = (const float*)d_in[10];
    const float* ln1_b       = (const float*)d_in[11];
    const float* wq          = (const float*)d_in[12];
    const float* bq          = (const float*)d_in[13];
    const float* wk          = (const float*)d_in[14];
    const float* bk          = (const float*)d_in[15];
    const float* wv          = (const float*)d_in[16];
    const float* bv          = (const float*)d_in[17];
    const float* wo          = (const float*)d_in[18];
    const float* bo          = (const float*)d_in[19];
    const float* ln2_g       = (const float*)d_in[20];
    const float* ln2_b       = (const float*)d_in[21];
    const float* w1          = (const float*)d_in[22];
    const float* b1          = (const float*)d_in[23];
    const float* w2          = (const float*)d_in[24];
    const float* b2          = (const float*)d_in[25];
    const float* lnf_g       = (const float*)d_in[26];
    const float* lnf_b       = (const float*)d_in[27];
    float* out = (float*)d_out;

    float *h, *bqkv;
    __half *hn, *qkv, *ctx, *ff, *wt;
    cudaGetSymbolAddress((void**)&h,    g_h);
    cudaGetSymbolAddress((void**)&hn,   g_hn);
    cudaGetSymbolAddress((void**)&qkv,  g_qkv);
    cudaGetSymbolAddress((void**)&ctx,  g_ctx);
    cudaGetSymbolAddress((void**)&ff,   g_ff);
    cudaGetSymbolAddress((void**)&wt,   g_wt);
    cudaGetSymbolAddress((void**)&bqkv, g_bqkv);

    cudaFuncSetAttribute((const void*)mma_gemm<0,0,__half>, cudaFuncAttributeMaxDynamicSharedMemorySize, SMEM_GEMM);
    cudaFuncSetAttribute((const void*)mma_gemm<0,1,float>,  cudaFuncAttributeMaxDynamicSharedMemorySize, SMEM_GEMM);
    cudaFuncSetAttribute((const void*)mma_gemm<1,0,__half>, cudaFuncAttributeMaxDynamicSharedMemorySize, SMEM_GEMM);

    // batched weight transposes (+ fp16 convert), z = layer
    dim3 tb(32, 8);
    transpose_f16_b<<<dim3(16,16,NLAYER), tb>>>(wq, wt,           DD, DD,  (size_t)DD*DD,  WT_LSTRIDE);
    transpose_f16_b<<<dim3(16,16,NLAYER), tb>>>(wk, wt + 262144,  DD, DD,  (size_t)DD*DD,  WT_LSTRIDE);
    transpose_f16_b<<<dim3(16,16,NLAYER), tb>>>(wv, wt + 524288,  DD, DD,  (size_t)DD*DD,  WT_LSTRIDE);
    transpose_f16_b<<<dim3(16,16,NLAYER), tb>>>(wo, wt + 786432,  DD, DD,  (size_t)DD*DD,  WT_LSTRIDE);
    transpose_f16_b<<<dim3(16,64,NLAYER), tb>>>(w1, wt + 1048576, DD, FFD, (size_t)DD*FFD, WT_LSTRIDE);
    transpose_f16_b<<<dim3(64,16,NLAYER), tb>>>(w2, wt + 2097152, FFD, DD, (size_t)FFD*DD, WT_LSTRIDE);
    concat_bias<<<dim3(6, NLAYER), 256>>>(bq, bk, bv, bqkv);

    embed_kernel<<<(TT*(DD/4))/256, 256>>>(x, emb, rate1, h);
    atom_kernel<<<NATOM, 128>>>(atoms_coord, atoms_token, atoms_index, batch_index,
                                emb, coord_w, coord_b, rate2, h);

    dim3 gD(DD/128, TT/128);       // (4, 512)
    dim3 gQKV(QKVD/128, TT/128);   // (12, 512)
    dim3 gF(FFD/128, TT/128);      // (16, 512)
    dim3 gFA(LL/128, BB*HH);       // (2, 2048)

    for (int l = 0; l < NLAYER; l++) {
        __half* base = wt + (size_t)l*WT_LSTRIDE;
        const __half* wtqkv = base;
        const __half* wto = base + 786432;
        const __half* wt1 = base + 1048576;
        const __half* wt2 = base + 2097152;

        ln_kernel<<<TT/8, 256>>>(h, hn, ln1_g + l*DD, ln1_b + l*DD);
        mma_gemm<0,0,__half><<<gQKV, 256, SMEM_GEMM>>>(DD, hn, wtqkv, bqkv + (size_t)l*QKVD,
                                                       nullptr, qkv, QKVD);
        flash_kernel<<<gFA, 256>>>(qkv, x, ctx);
        mma_gemm<0,1,float><<<gD, 256, SMEM_GEMM>>>(DD, ctx, wto, bo + l*DD, h, h, DD);
        ln_kernel<<<TT/8, 256>>>(h, hn, ln2_g + l*DD, ln2_b + l*DD);
        mma_gemm<1,0,__half><<<gF, 256, SMEM_GEMM>>>(DD, hn, wt1, b1 + l*FFD, nullptr, ff, FFD);
        mma_gemm<0,1,float><<<gD, 256, SMEM_GEMM>>>(FFD, ff, wt2, b2 + l*DD, h, h, DD);
    }
    lnf_kernel<<<TT/8, 256>>>(h, out, lnf_g, lnf_b);
}